// round 4
// baseline (speedup 1.0000x reference)
#include <cuda_runtime.h>
#include <cuda_bf16.h>
#include <math.h>

// ---------------------------------------------------------------------------
// Problem constants (DeepseekV3 MLA prefill, B=1, S=2048)
// ---------------------------------------------------------------------------
#define S_LEN  2048
#define HID    2048
#define NH     16
#define NOPE   128
#define ROPE_D 64
#define QHD    192     // NOPE + ROPE
#define VD     128
#define QLR    1536
#define KVLR   512
#define CKVD   576     // KVLR + ROPE

// ---------------------------------------------------------------------------
// Scratch (static __device__ arrays — no runtime allocation)
// ---------------------------------------------------------------------------
__device__ float g_qa  [S_LEN * QLR];          // hidden @ Wqa (normed in place)
__device__ float g_q   [S_LEN * NH * QHD];     // q_a @ Wqb, RoPE applied in place
__device__ float g_ckv [S_LEN * CKVD];         // hidden @ Wkva (raw)
__device__ float g_ckvn[S_LEN * KVLR];         // rmsnorm(c_kv)
__device__ float g_kpe [S_LEN * ROPE_D];       // roped shared k_pe
__device__ float g_kv  [S_LEN * NH * (NOPE + VD)]; // ckvn @ Wkvb: per head [k_nope|v]
__device__ float g_attn[S_LEN * NH * VD];      // attention output (s, h*128+d)

// ---------------------------------------------------------------------------
// Generic tiled GEMM: C[M,N] = A[M,K] @ B[K,N], row-major, fp32.
// 128x128 block, 16 k-step, 256 threads, 8x8 register microtile.
// Requires: M % 128 == 0, K % 16 == 0. N is guarded.
// ---------------------------------------------------------------------------
__global__ void __launch_bounds__(256) gemm_kernel(
    float* __restrict__ C, const float* __restrict__ A, const float* __restrict__ B,
    int M, int N, int K, int lda, int ldb, int ldc)
{
    __shared__ float As[16][128];
    __shared__ float Bs[16][128];

    const int tid = threadIdx.x;
    const int tx  = tid & 15;
    const int ty  = tid >> 4;
    const int m0  = blockIdx.y * 128;
    const int n0  = blockIdx.x * 128;

    float c[8][8];
#pragma unroll
    for (int i = 0; i < 8; i++)
#pragma unroll
        for (int j = 0; j < 8; j++) c[i][j] = 0.f;

    for (int k0 = 0; k0 < K; k0 += 16) {
        // Load A tile (128 rows x 16 k) transposed into As[k][m]
#pragma unroll
        for (int t = 0; t < 2; t++) {
            int v  = tid * 2 + t;           // 0..511
            int m  = v >> 2;
            int kq = v & 3;
            float4 a = *(const float4*)(A + (size_t)(m0 + m) * lda + k0 + kq * 4);
            As[kq * 4 + 0][m] = a.x;
            As[kq * 4 + 1][m] = a.y;
            As[kq * 4 + 2][m] = a.z;
            As[kq * 4 + 3][m] = a.w;
        }
        // Load B tile (16 k x 128 n)
#pragma unroll
        for (int t = 0; t < 2; t++) {
            int v  = tid + t * 256;         // 0..511
            int k  = v >> 5;
            int nq = v & 31;
            int n  = n0 + nq * 4;
            float4 b;
            if (n + 3 < N) {
                b = *(const float4*)(B + (size_t)(k0 + k) * ldb + n);
            } else {
                const float* bp = B + (size_t)(k0 + k) * ldb;
                b.x = (n + 0 < N) ? bp[n + 0] : 0.f;
                b.y = (n + 1 < N) ? bp[n + 1] : 0.f;
                b.z = (n + 2 < N) ? bp[n + 2] : 0.f;
                b.w = (n + 3 < N) ? bp[n + 3] : 0.f;
            }
            *(float4*)&Bs[k][nq * 4] = b;
        }
        __syncthreads();

#pragma unroll
        for (int k = 0; k < 16; k++) {
            float4 a0 = *(float4*)&As[k][ty * 8];
            float4 a1 = *(float4*)&As[k][ty * 8 + 4];
            float4 b0 = *(float4*)&Bs[k][tx * 8];
            float4 b1 = *(float4*)&Bs[k][tx * 8 + 4];
            float av[8] = {a0.x, a0.y, a0.z, a0.w, a1.x, a1.y, a1.z, a1.w};
            float bv[8] = {b0.x, b0.y, b0.z, b0.w, b1.x, b1.y, b1.z, b1.w};
#pragma unroll
            for (int i = 0; i < 8; i++)
#pragma unroll
                for (int j = 0; j < 8; j++) c[i][j] += av[i] * bv[j];
        }
        __syncthreads();
    }

#pragma unroll
    for (int i = 0; i < 8; i++) {
        int m = m0 + ty * 8 + i;
#pragma unroll
        for (int j = 0; j < 8; j++) {
            int n = n0 + tx * 8 + j;
            if (n < N) C[(size_t)m * ldc + n] = c[i][j];
        }
    }
}

// ---------------------------------------------------------------------------
// RMSNorm: one block per row. out[i] = w[i] * x[i] * rsqrt(mean(x^2) + eps)
// ---------------------------------------------------------------------------
__global__ void __launch_bounds__(256) rmsnorm_kernel(
    float* __restrict__ out, const float* __restrict__ in,
    const float* __restrict__ w, int D, int ldin, int ldout)
{
    const int row = blockIdx.x;
    const float* x = in + (size_t)row * ldin;
    float* y = out + (size_t)row * ldout;

    float s = 0.f;
    for (int i = threadIdx.x; i < D; i += 256) {
        float v = x[i];
        s += v * v;
    }
#pragma unroll
    for (int o = 16; o; o >>= 1) s += __shfl_xor_sync(0xffffffffu, s, o);

    __shared__ float red[8];
    __shared__ float inv_s;
    if ((threadIdx.x & 31) == 0) red[threadIdx.x >> 5] = s;
    __syncthreads();
    if (threadIdx.x == 0) {
        float t = 0.f;
#pragma unroll
        for (int i = 0; i < 8; i++) t += red[i];
        inv_s = rsqrtf(t / (float)D + 1e-6f);
    }
    __syncthreads();
    float inv = inv_s;
    for (int i = threadIdx.x; i < D; i += 256) y[i] = w[i] * (x[i] * inv);
}

// ---------------------------------------------------------------------------
// RoPE (deinterleave + rotate_half fused):
//   y[j] = x[2j], y[j+32] = x[2j+1];  cos/sin period 32
//   out[j]    = x[2j]  *c - x[2j+1]*s
//   out[j+32] = x[2j+1]*c + x[2j]  *s
// q_pe updated in place (16 heads, cols [128,192) of each 192-wide head slot),
// k_pe read from raw ckv tail, written to g_kpe.
// Block = one token, 544 threads = 16 head-warps + 1 kpe warp.
// ---------------------------------------------------------------------------
__global__ void rope_kernel(float* __restrict__ q, float* __restrict__ kpe,
                            const float* __restrict__ ckv,
                            const int* __restrict__ pos_ids)
{
    const int srow = blockIdx.x;
    const int tid  = threadIdx.x;
    const int j    = tid & 31;

    const float pos  = (float)pos_ids[srow];
    const float freq = __expf(-((2.f * (float)j) / 64.f) * logf(10000.f));
    const float ang  = pos * freq;
    float cv, sv;
    __sincosf(ang, &sv, &cv);

    if (tid < NH * 32) {
        const int h = tid >> 5;
        float* base = q + (size_t)srow * (NH * QHD) + h * QHD + NOPE;
        float x0 = base[2 * j];
        float x1 = base[2 * j + 1];
        __syncwarp();
        base[j]      = x0 * cv - x1 * sv;
        base[32 + j] = x1 * cv + x0 * sv;
    } else {
        const float* src = ckv + (size_t)srow * CKVD + KVLR;
        float x0 = src[2 * j];
        float x1 = src[2 * j + 1];
        float* dst = kpe + (size_t)srow * ROPE_D;
        dst[j]      = x0 * cv - x1 * sv;
        dst[32 + j] = x1 * cv + x0 * sv;
    }
}

// ---------------------------------------------------------------------------
// Causal flash attention, fp32.
//   BM=BN=64, D=192 (nope128 + rope64), DV=128, 256 threads.
//   Thread (ty,tx), ty=tid/16, tx=tid%16:
//     scores: 4 q-rows (ty*4..) x 4 k-cols (tx*4..)
//     PV/acc: same 4 q-rows x 8 v-dims (tx*8..)
//   Row softmax state reduced across the 16 tx threads via shfl (width 16).
// ---------------------------------------------------------------------------
#define FA_BM 64
#define FA_BN 64
#define FA_D  192
#define FA_DP 196   // padded row for sQ/sK
#define FA_DV 128
#define FA_SMEM_FLOATS (FA_BM*FA_DP + FA_BN*FA_DP + FA_BN*FA_DV + FA_BM*FA_BN)

__global__ void __launch_bounds__(256) flash_kernel(
    float* __restrict__ O, const float* __restrict__ Q,
    const float* __restrict__ KV, const float* __restrict__ KPE)
{
    extern __shared__ float sm[];
    float* sQ = sm;                           // 64 x 196
    float* sK = sQ + FA_BM * FA_DP;           // 64 x 196
    float* sV = sK + FA_BN * FA_DP;           // 64 x 128
    float* sP = sV + FA_BN * FA_DV;           // 64 x 64

    const int tid = threadIdx.x;
    const int tx  = tid & 15;
    const int ty  = tid >> 4;
    const int h   = blockIdx.y;
    const int qb  = blockIdx.x;
    const int q0  = qb * FA_BM;

    // Load Q tile (64 x 192) as float4
    for (int v = tid; v < FA_BM * 48; v += 256) {
        int r = v / 48, cc = v % 48;
        float4 val = *(const float4*)(Q + (size_t)(q0 + r) * (NH * QHD) + h * QHD + cc * 4);
        *(float4*)(sQ + r * FA_DP + cc * 4) = val;
    }

    float acc[4][8];
    float m_i[4], l_i[4];
#pragma unroll
    for (int i = 0; i < 4; i++) {
        m_i[i] = -1e30f;
        l_i[i] = 0.f;
#pragma unroll
        for (int j = 0; j < 8; j++) acc[i][j] = 0.f;
    }
    const float scale = rsqrtf((float)QHD);

    for (int kb = 0; kb <= qb; kb++) {
        const int k0 = kb * FA_BN;
        __syncthreads();   // previous PV done with sV/sP
        // Load K tile: cols [0,128) = k_nope, [128,192) = shared roped k_pe
        for (int v = tid; v < FA_BN * 48; v += 256) {
            int r = v / 48, cc = v % 48;
            float4 val;
            if (cc < 32)
                val = *(const float4*)(KV + (size_t)(k0 + r) * (NH * 256) + h * 256 + cc * 4);
            else
                val = *(const float4*)(KPE + (size_t)(k0 + r) * ROPE_D + (cc - 32) * 4);
            *(float4*)(sK + r * FA_DP + cc * 4) = val;
        }
        // Load V tile (64 x 128)
        for (int v = tid; v < FA_BN * 32; v += 256) {
            int r = v / 32, cc = v % 32;
            float4 val = *(const float4*)(KV + (size_t)(k0 + r) * (NH * 256) + h * 256 + NOPE + cc * 4);
            *(float4*)(sV + r * FA_DV + cc * 4) = val;
        }
        __syncthreads();

        // Scores: 4x4 microtile
        float s4[4][4];
#pragma unroll
        for (int i = 0; i < 4; i++)
#pragma unroll
            for (int j = 0; j < 4; j++) s4[i][j] = 0.f;

#pragma unroll 4
        for (int d = 0; d < FA_D; d += 4) {
            float4 qv[4], kv4[4];
#pragma unroll
            for (int i = 0; i < 4; i++) qv[i]  = *(float4*)(sQ + (ty * 4 + i) * FA_DP + d);
#pragma unroll
            for (int j = 0; j < 4; j++) kv4[j] = *(float4*)(sK + (tx * 4 + j) * FA_DP + d);
#pragma unroll
            for (int i = 0; i < 4; i++)
#pragma unroll
                for (int j = 0; j < 4; j++)
                    s4[i][j] += qv[i].x * kv4[j].x + qv[i].y * kv4[j].y
                              + qv[i].z * kv4[j].z + qv[i].w * kv4[j].w;
        }

        // Scale + causal mask + online softmax
#pragma unroll
        for (int i = 0; i < 4; i++) {
            const int qi = q0 + ty * 4 + i;
            float rmax = -1e30f;
#pragma unroll
            for (int j = 0; j < 4; j++) {
                int kj = k0 + tx * 4 + j;
                float v = (kj <= qi) ? s4[i][j] * scale : -1e30f;
                s4[i][j] = v;
                rmax = fmaxf(rmax, v);
            }
#pragma unroll
            for (int o = 8; o; o >>= 1)
                rmax = fmaxf(rmax, __shfl_xor_sync(0xffffffffu, rmax, o, 16));

            float m_new = fmaxf(m_i[i], rmax);
            float alpha = __expf(m_i[i] - m_new);
            float rsum = 0.f;
#pragma unroll
            for (int j = 0; j < 4; j++) {
                float p = __expf(s4[i][j] - m_new);
                s4[i][j] = p;
                rsum += p;
            }
#pragma unroll
            for (int o = 8; o; o >>= 1)
                rsum += __shfl_xor_sync(0xffffffffu, rsum, o, 16);

            l_i[i] = l_i[i] * alpha + rsum;
            m_i[i] = m_new;
#pragma unroll
            for (int j = 0; j < 8; j++) acc[i][j] *= alpha;
#pragma unroll
            for (int j = 0; j < 4; j++)
                sP[(ty * 4 + i) * FA_BN + tx * 4 + j] = s4[i][j];
        }
        __syncthreads();

        // PV: acc[4][8] += sP[4 rows][64] @ sV[64][8 dims]
#pragma unroll 4
        for (int kc = 0; kc < FA_BN; kc++) {
            float4 v0 = *(float4*)(sV + kc * FA_DV + tx * 8);
            float4 v1 = *(float4*)(sV + kc * FA_DV + tx * 8 + 4);
#pragma unroll
            for (int i = 0; i < 4; i++) {
                float p = sP[(ty * 4 + i) * FA_BN + kc];
                acc[i][0] += p * v0.x; acc[i][1] += p * v0.y;
                acc[i][2] += p * v0.z; acc[i][3] += p * v0.w;
                acc[i][4] += p * v1.x; acc[i][5] += p * v1.y;
                acc[i][6] += p * v1.z; acc[i][7] += p * v1.w;
            }
        }
    }

    // Epilogue: O[(q0+qr), h*128 + tx*8 + j] = acc / l
#pragma unroll
    for (int i = 0; i < 4; i++) {
        float inv_l = 1.f / l_i[i];
        float* op = O + (size_t)(q0 + ty * 4 + i) * (NH * VD) + h * VD + tx * 8;
#pragma unroll
        for (int j = 0; j < 8; j++) op[j] = acc[i][j] * inv_l;
    }
}

// ---------------------------------------------------------------------------
// Launch
// ---------------------------------------------------------------------------
extern "C" void kernel_launch(void* const* d_in, const int* in_sizes, int n_in,
                              void* d_out, int out_size)
{
    const float* hidden = (const float*)d_in[0];
    const int*   pos    = (const int*)d_in[1];
    const float* Wqa    = (const float*)d_in[2];
    const float* qa_ln  = (const float*)d_in[3];
    const float* Wqb    = (const float*)d_in[4];
    const float* Wkva   = (const float*)d_in[5];
    const float* kv_ln  = (const float*)d_in[6];
    const float* Wkvb   = (const float*)d_in[7];
    const float* Wo     = (const float*)d_in[8];
    float* out = (float*)d_out;

    float *qa, *q, *ckv, *ckvn, *kpe, *kv, *attn;
    cudaGetSymbolAddress((void**)&qa,   g_qa);
    cudaGetSymbolAddress((void**)&q,    g_q);
    cudaGetSymbolAddress((void**)&ckv,  g_ckv);
    cudaGetSymbolAddress((void**)&ckvn, g_ckvn);
    cudaGetSymbolAddress((void**)&kpe,  g_kpe);
    cudaGetSymbolAddress((void**)&kv,   g_kv);
    cudaGetSymbolAddress((void**)&attn, g_attn);

    // 1) q_a = hidden @ Wqa   [2048 x 1536]
    gemm_kernel<<<dim3(QLR / 128, S_LEN / 128), 256>>>(
        qa, hidden, Wqa, S_LEN, QLR, HID, HID, QLR, QLR);
    // 2) ckv = hidden @ Wkva  [2048 x 576]
    gemm_kernel<<<dim3((CKVD + 127) / 128, S_LEN / 128), 256>>>(
        ckv, hidden, Wkva, S_LEN, CKVD, HID, HID, CKVD, CKVD);
    // 3) rmsnorm(q_a) in place
    rmsnorm_kernel<<<S_LEN, 256>>>(qa, qa, qa_ln, QLR, QLR, QLR);
    // 4) rmsnorm(c_kv) -> ckvn
    rmsnorm_kernel<<<S_LEN, 256>>>(ckvn, ckv, kv_ln, KVLR, CKVD, KVLR);
    // 5) q = q_a @ Wqb        [2048 x 3072]
    gemm_kernel<<<dim3((NH * QHD) / 128, S_LEN / 128), 256>>>(
        q, qa, Wqb, S_LEN, NH * QHD, QLR, QLR, NH * QHD, NH * QHD);
    // 6) kv = ckvn @ Wkvb     [2048 x 4096]
    gemm_kernel<<<dim3((NH * 256) / 128, S_LEN / 128), 256>>>(
        kv, ckvn, Wkvb, S_LEN, NH * 256, KVLR, KVLR, NH * 256, NH * 256);
    // 7) RoPE on q_pe (in place) and k_pe (ckv tail -> g_kpe)
    rope_kernel<<<S_LEN, (NH + 1) * 32>>>(q, kpe, ckv, pos);
    // 8) causal flash attention -> g_attn
    size_t fa_smem = (size_t)FA_SMEM_FLOATS * sizeof(float);
    cudaFuncSetAttribute(flash_kernel,
                         cudaFuncAttributeMaxDynamicSharedMemorySize, (int)fa_smem);
    flash_kernel<<<dim3(S_LEN / FA_BM, NH), 256, fa_smem>>>(attn, q, kv, kpe);
    // 9) out = attn @ Wo      [2048 x 2048]
    gemm_kernel<<<dim3(HID / 128, S_LEN / 128), 256>>>(
        out, attn, Wo, S_LEN, HID, NH * VD, NH * VD, HID, HID);
}